// round 16
// baseline (speedup 1.0000x reference)
#include <cuda_runtime.h>
#include <cstdint>

// Problem constants
#define Nn 64
#define Cc 64
#define Tt 300
#define Vv 25
#define Ss 3
#define TV 7500
#define NS 192
#define CNT_BN 480000.0f
#define EPS_BN 1e-5f

// ---------------- scratch -----------------------------------------------------
__device__ float g_scores[NS * 625];
__device__ float g_adapt[NS * 700];               // [ns][v][w pad 28]
__device__ float g_y[(size_t)Nn * Cc * TV];
__device__ float g_bdsum[Cc];
__device__ float g_stats[2 * Cc];

#define MMA_TF32(d, a0, a1, a2, a3, b0, b1)                                   \
    asm volatile(                                                              \
        "mma.sync.aligned.m16n8k8.row.col.f32.tf32.tf32.f32 "                  \
        "{%0,%1,%2,%3}, {%4,%5,%6,%7}, {%8,%9}, {%0,%1,%2,%3};"                \
        : "+f"((d)[0]), "+f"((d)[1]), "+f"((d)[2]), "+f"((d)[3])               \
        : "r"(a0), "r"(a1), "r"(a2), "r"(a3), "r"(b0), "r"(b1))

// ---------------- K0: prep ----------------------------------------------------
__global__ void k_prep(const float* __restrict__ wd, const float* __restrict__ bd) {
    int idx = blockIdx.x * 256 + threadIdx.x;
    if (idx < NS * 625) g_scores[idx] = 0.f;
    if (idx < Cc) g_bdsum[idx] = bd[idx] + bd[64 + idx] + bd[128 + idx];
    if (idx < 2 * Cc) g_stats[idx] = 0.f;
}

// ---------------- K1: tensor projection + scores, shift-only (R14) ------------
#define KA_SMEM_FLOATS 24992
__global__ void __launch_bounds__(256, 2)
k_attn_mma(const float* __restrict__ x,
           const float* __restrict__ wa, const float* __restrict__ ba,
           const float* __restrict__ wb, const float* __restrict__ bb) {
    extern __shared__ float sm[];
    float* wabT = sm;             // [32][68]
    float* bias = sm + 2176;      // [32]
    float* xs   = sm + 2208;      // 2 x [64][136] : [c][tp*32+v]
    float* abA  = sm + 19616;     // [32][84]
    float* abB  = sm + 22304;     // [32][84]

    int ns = blockIdx.x;
    int n = ns / Ss, s = ns - n * Ss;
    int tid = threadIdx.x;
    int wid = tid >> 5, lane = tid & 31;
    int g = lane >> 2, tig = lane & 3;

    for (int j = tid; j < 2048; j += 256) {
        int row = j >> 6, k = j & 63;
        wabT[row * 68 + k] = (row < 16) ? wa[(s * 16 + row) * 64 + k]
                                        : wb[(s * 16 + row - 16) * 64 + k];
    }
    if (tid < 32) bias[tid] = (tid < 16) ? ba[s * 16 + tid] : bb[s * 16 + tid - 16];

    const float* xn = x + (size_t)n * Cc * TV;
    int tcb = blockIdx.y * 100;

    if (lane < 25) {
#pragma unroll 1
        for (int rr = 0; rr < 8; rr++) {
            int c = wid * 8 + rr;
            const float* xg = xn + (size_t)c * TV + tcb * 25;
            float* xb = xs + c * 136;
#pragma unroll
            for (int tp = 0; tp < 4; tp++)
                xb[tp * 32 + lane] = xg[tp * 25 + lane];
        }
    }
    __syncthreads();

    float sc[4] = {0.f, 0.f, 0.f, 0.f};
    int smt = wid >> 2, snt = wid & 3;

    for (int b = 0; b < 25; b++) {
        int buf = b & 1;
        float* xb  = xs + buf * 8704;
        float* xnb = xs + (buf ^ 1) * 8704;

        if (b < 24 && lane < 25) {
            int tb = tcb + (b + 1) * 4;
#pragma unroll 1
            for (int rr = 0; rr < 8; rr++) {
                int c = wid * 8 + rr;
                const float* xg = xn + (size_t)c * TV + tb * 25;
                float* xo = xnb + c * 136;
#pragma unroll
                for (int tp = 0; tp < 4; tp++)
                    xo[tp * 32 + lane] = xg[tp * 25 + lane];
            }
        }
        float dd[2][2][4];
#pragma unroll
        for (int mt = 0; mt < 2; mt++)
#pragma unroll
            for (int lnt = 0; lnt < 2; lnt++)
#pragma unroll
                for (int e = 0; e < 4; e++) dd[mt][lnt][e] = 0.f;
#pragma unroll
        for (int ks = 0; ks < 8; ks++) {
            int k0 = ks * 8;
            uint32_t af[2][4];
#pragma unroll
            for (int mt = 0; mt < 2; mt++) {
                int r = mt * 16 + g;
                af[mt][0] = __float_as_uint(wabT[r * 68 + k0 + tig]);
                af[mt][1] = __float_as_uint(wabT[(r + 8) * 68 + k0 + tig]);
                af[mt][2] = __float_as_uint(wabT[r * 68 + k0 + 4 + tig]);
                af[mt][3] = __float_as_uint(wabT[(r + 8) * 68 + k0 + 4 + tig]);
            }
#pragma unroll
            for (int lnt = 0; lnt < 2; lnt++) {
                int col = (wid * 2 + lnt) * 8 + g;
                uint32_t b0 = __float_as_uint(xb[(k0 + tig) * 136 + col]);
                uint32_t b1 = __float_as_uint(xb[(k0 + 4 + tig) * 136 + col]);
#pragma unroll
                for (int mt = 0; mt < 2; mt++)
                    MMA_TF32(dd[mt][lnt], af[mt][0], af[mt][1], af[mt][2], af[mt][3], b0, b1);
            }
        }
#pragma unroll
        for (int mt = 0; mt < 2; mt++) {
            float* dst = mt ? abB : abA;
#pragma unroll
            for (int lnt = 0; lnt < 2; lnt++)
#pragma unroll
                for (int e = 0; e < 4; e++) {
                    int i2 = g + ((e >> 1) << 3);
                    int cg = (wid * 2 + lnt) * 8 + tig * 2 + (e & 1);
                    int v = cg & 31, tp = cg >> 5;
                    if (v < 25)
                        dst[v * 84 + i2 * 4 + tp] = dd[mt][lnt][e] + bias[mt * 16 + i2];
                }
        }
        __syncthreads();

        {
            int va = smt * 16 + g;
            int wcol = snt * 8 + g;
#pragma unroll
            for (int ks = 0; ks < 8; ks++) {
                int k0 = ks * 8;
                uint32_t a0 = __float_as_uint(abA[va * 84 + k0 + tig]);
                uint32_t a1 = __float_as_uint(abA[(va + 8) * 84 + k0 + tig]);
                uint32_t a2 = __float_as_uint(abA[va * 84 + k0 + 4 + tig]);
                uint32_t a3 = __float_as_uint(abA[(va + 8) * 84 + k0 + 4 + tig]);
                uint32_t b0 = __float_as_uint(abB[wcol * 84 + k0 + tig]);
                uint32_t b1 = __float_as_uint(abB[wcol * 84 + k0 + 4 + tig]);
                MMA_TF32(sc, a0, a1, a2, a3, b0, b1);
            }
        }
        __syncthreads();
    }

    {
        int v = smt * 16 + g;
        int w = snt * 8 + tig * 2;
        float* gs = g_scores + ns * 625;
        if (v < 25) {
            if (w < 25)     atomicAdd(&gs[v * 25 + w], sc[0]);
            if (w + 1 < 25) atomicAdd(&gs[v * 25 + w + 1], sc[1]);
        }
        if (v + 8 < 25) {
            if (w < 25)     atomicAdd(&gs[(v + 8) * 25 + w], sc[2]);
            if (w + 1 < 25) atomicAdd(&gs[(v + 8) * 25 + w + 1], sc[3]);
        }
    }
}

// ---------------- K2: softmax + adapt (padded 28) -----------------------------
__global__ void k_softmax(const float* __restrict__ A, const float* __restrict__ W) {
    int ns = blockIdx.x;
    int s = ns % Ss;
    int w = threadIdx.x;
    if (w >= 28) return;
    if (w >= Vv) {
#pragma unroll
        for (int v = 0; v < Vv; v++) g_adapt[ns * 700 + v * 28 + w] = 0.f;
        return;
    }
    float col[Vv];
    const float inv = 1.f / 4800.f;
    float m = -1e30f;
#pragma unroll
    for (int v = 0; v < Vv; v++) {
        col[v] = g_scores[ns * 625 + v * 25 + w] * inv;
        m = fmaxf(m, col[v]);
    }
    float sum = 0.f;
#pragma unroll
    for (int v = 0; v < Vv; v++) { col[v] = __expf(col[v] - m); sum += col[v]; }
    float r = 1.f / sum;
#pragma unroll
    for (int v = 0; v < Vv; v++) {
        int off = s * 625 + v * 25 + w;
        g_adapt[ns * 700 + v * 28 + w] = A[off] + W[off] + col[v] * r;
    }
}

// ---------------- K3: all-tensor fused; R13 GEMM tiling + balanced z ----------
#define FM_SMEM_FLOATS 15936
#define XS0 0
#define ZT0 2880
#define WDF0 9408
#define AD0 12480
__global__ void __launch_bounds__(256, 3)
k_fused_mma(const float* __restrict__ x, const float* __restrict__ wd) {
    extern __shared__ float dsm[];
    float* ysm = dsm;

    int n = blockIdx.x;
    int t0 = blockIdx.y * 5;
    int tid = threadIdx.x;
    int wid = tid >> 5, lane = tid & 31;
    int g = lane >> 2, tig = lane & 3;

    float d[8][4];
#pragma unroll
    for (int nt = 0; nt < 8; nt++)
#pragma unroll
        for (int e = 0; e < 4; e++) d[nt][e] = 0.f;

    int otile = wid & 3, nhalf = wid >> 2;
    int col0 = nhalf * 64;

    // ---- prologue: adT, xs (both bufs zero + chunk0 data), wdf(0) ----
    for (int j = tid; j < 3456; j += 256) {
        int s = j / 1152, r = j - s * 1152;
        int w = r / 36, i = r - w * 36;
        float val = 0.f;
        if (i < 32 && w < 25) {
            int v = (i & 7) * 4 + (i >> 3);
            if (v < 25) val = g_adapt[n * 2100 + s * 700 + v * 28 + w];
        }
        dsm[AD0 + j] = val;
    }
    for (int j = tid; j < 2880; j += 256) dsm[XS0 + j] = 0.f;
    __syncthreads();
    if (lane < 25) {
        int tigv = lane & 3, uv = lane >> 2;
        const float* xg = x + (size_t)(n * Cc + wid) * TV + t0 * 25;
        float* xb = dsm + XS0 + wid * 180;
#pragma unroll
        for (int tp = 0; tp < 5; tp++)
            xb[tp * 36 + tigv * 8 + uv] = xg[tp * 25 + lane];
    }
    {   // wdf(0)
        float* wdn = dsm + WDF0;
        int ot = wid & 3, hf = wid >> 2;
#pragma unroll
        for (int q2 = 0; q2 < 6; q2++) {
            int i = hf * 6 + q2;
            int reg = i & 3, ks2 = i >> 2;
            int o = ot * 16 + g + ((reg & 1) << 3);
            int kk = ks2 * 8 + tig + ((reg >> 1) << 2);
            wdn[(ot * 32 + lane) * 12 + i] =
                wd[(size_t)(((kk >> 3) << 6) + o) * 64 + (kk & 7)];
        }
    }
    __syncthreads();

    for (int c = 0; c < 8; c++) {
        int buf = c & 1, nbuf = buf ^ 1;
        const float* xsb = dsm + XS0 + buf * 1440;
        float* ztb = dsm + ZT0 + buf * 3264;

        // ---- phase 1: every warp stages one cc of x(c+1) + z-unit(s) ----
        if (c < 7 && lane < 25) {
            int tigv = lane & 3, uv = lane >> 2;
            const float* xg = x + (size_t)(n * Cc + (c + 1) * 8 + wid) * TV + t0 * 25;
            float* xb = dsm + XS0 + nbuf * 1440 + wid * 180;
#pragma unroll
            for (int tp = 0; tp < 5; tp++)
                xb[tp * 36 + tigv * 8 + uv] = xg[tp * 25 + lane];
        }
        {
            int nunits = (wid == 7) ? 2 : 1;
#pragma unroll 1
            for (int ui = 0; ui < nunits; ui++) {
                int u = (ui == 0) ? wid : 8;
                int s = u / 3, mt = u - s * 3;
                const float* adTs = dsm + AD0 + s * 1152;
                int m0 = mt * 16 + g, m1 = m0 + 8;
                int cc0 = m0 / 5, tp0 = m0 - cc0 * 5;
                bool hv = (m1 < 40);
                int m1c = hv ? m1 : 0;
                int cc1 = m1c / 5, tp1 = m1c - cc1 * 5;
                float lo[8], hi[8];
                const float* pa = xsb + cc0 * 180 + tp0 * 36 + tig * 8;
                *(float4*)&lo[0] = *(const float4*)pa;
                *(float4*)&lo[4] = *(const float4*)(pa + 4);
                if (hv) {
                    const float* pb = xsb + cc1 * 180 + tp1 * 36 + tig * 8;
                    *(float4*)&hi[0] = *(const float4*)pb;
                    *(float4*)&hi[4] = *(const float4*)(pb + 4);
                } else {
#pragma unroll
                    for (int u2 = 0; u2 < 8; u2++) hi[u2] = 0.f;
                }
#pragma unroll
                for (int nt = 0; nt < 4; nt++) {
                    float adv[8];
                    const float* pc = adTs + (nt * 8 + g) * 36 + tig * 8;
                    *(float4*)&adv[0] = *(const float4*)pc;
                    *(float4*)&adv[4] = *(const float4*)(pc + 4);
                    float dz[4] = {0.f, 0.f, 0.f, 0.f};
#pragma unroll
                    for (int ks = 0; ks < 4; ks++) {
                        MMA_TF32(dz,
                                 __float_as_uint(lo[2 * ks]), __float_as_uint(hi[2 * ks]),
                                 __float_as_uint(lo[2 * ks + 1]), __float_as_uint(hi[2 * ks + 1]),
                                 __float_as_uint(adv[2 * ks]), __float_as_uint(adv[2 * ks + 1]));
                    }
                    int w0c = nt * 8 + tig * 2;
                    if (w0c < 25)     ztb[(s * 8 + cc0) * 136 + tp0 * 25 + w0c] = dz[0];
                    if (w0c + 1 < 25) ztb[(s * 8 + cc0) * 136 + tp0 * 25 + w0c + 1] = dz[1];
                    if (hv) {
                        if (w0c < 25)     ztb[(s * 8 + cc1) * 136 + tp1 * 25 + w0c] = dz[2];
                        if (w0c + 1 < 25) ztb[(s * 8 + cc1) * 136 + tp1 * 25 + w0c + 1] = dz[3];
                    }
                }
            }
        }
        __syncthreads();   // the ONLY barrier per chunk

        // ---- phase 2: wdf stage (c+1) + gemm(c) ----
        if (c < 7) {
            int c0n = (c + 1) * 8;
            float* wdn = dsm + WDF0 + nbuf * 1536;
            int ot = wid & 3, hf = wid >> 2;
#pragma unroll
            for (int q2 = 0; q2 < 6; q2++) {
                int i = hf * 6 + q2;
                int reg = i & 3, ks2 = i >> 2;
                int o = ot * 16 + g + ((reg & 1) << 3);
                int kk = ks2 * 8 + tig + ((reg >> 1) << 2);
                wdn[(ot * 32 + lane) * 12 + i] =
                    wd[(size_t)(((kk >> 3) << 6) + o) * 64 + c0n + (kk & 7)];
            }
        }
        {
            const float* wdb = dsm + WDF0 + buf * 1536;
            float afr[12];
            const float* pw = wdb + (otile * 32 + lane) * 12;
            *(float4*)&afr[0] = *(const float4*)pw;
            *(float4*)&afr[4] = *(const float4*)(pw + 4);
            *(float4*)&afr[8] = *(const float4*)(pw + 8);
#pragma unroll
            for (int ks = 0; ks < 3; ks++) {
                int k0 = ks * 8;
                uint32_t a0 = __float_as_uint(afr[ks * 4 + 0]);
                uint32_t a1 = __float_as_uint(afr[ks * 4 + 1]);
                uint32_t a2 = __float_as_uint(afr[ks * 4 + 2]);
                uint32_t a3 = __float_as_uint(afr[ks * 4 + 3]);
#pragma unroll
                for (int nt = 0; nt < 8; nt++) {
                    int nc = col0 + nt * 8 + g;
                    uint32_t b0 = __float_as_uint(ztb[(k0 + tig) * 136 + nc]);
                    uint32_t b1 = __float_as_uint(ztb[(k0 + 4 + tig) * 136 + nc]);
                    MMA_TF32(d[nt], a0, a1, a2, a3, b0, b1);
                }
            }
        }
    }

    // ---- epilogue ----
    __syncthreads();
#pragma unroll
    for (int nt = 0; nt < 8; nt++) {
        int colb = col0 + nt * 8 + tig * 2;
        int r0 = otile * 16 + g;
        ysm[r0 * 132 + colb]           = d[nt][0];
        ysm[r0 * 132 + colb + 1]       = d[nt][1];
        ysm[(r0 + 8) * 132 + colb]     = d[nt][2];
        ysm[(r0 + 8) * 132 + colb + 1] = d[nt][3];
    }
    __syncthreads();
#pragma unroll 1
    for (int rr = 0; rr < 8; rr++) {
        int o = wid * 8 + rr;
        float bias = g_bdsum[o];
        float s1 = 0.f, s2 = 0.f;
        float* yp = g_y + (size_t)(n * Cc + o) * TV + t0 * 25;
        for (int col = lane; col < 125; col += 32) {
            float v = ysm[o * 132 + col] + bias;
            yp[col] = v;
            s1 += v; s2 += v * v;
        }
#pragma unroll
        for (int dd2 = 16; dd2 > 0; dd2 >>= 1) {
            s1 += __shfl_xor_sync(0xffffffffu, s1, dd2);
            s2 += __shfl_xor_sync(0xffffffffu, s2, dd2);
        }
        if (lane == 0) {
            atomicAdd(&g_stats[o], s1);
            atomicAdd(&g_stats[64 + o], s2);
        }
    }
}

// ---------------- K4: normalize + gamma/beta + residual + relu ----------------
__global__ void k_final(const float* __restrict__ x,
                        const float* __restrict__ gamma, const float* __restrict__ beta,
                        float* __restrict__ out) {
    int i4 = blockIdx.x * 256 + threadIdx.x;
    int c = (i4 / 1875) & 63;
    float s1 = g_stats[c], s2 = g_stats[64 + c];
    float mean = s1 / CNT_BN;
    float var = s2 / CNT_BN - mean * mean;
    float scale = gamma[c] * rsqrtf(var + EPS_BN);
    float bet = beta[c];
    float4 yv = ((const float4*)g_y)[i4];
    float4 xv = ((const float4*)x)[i4];
    float4 o;
    o.x = fmaxf(0.f, (yv.x - mean) * scale + bet + xv.x);
    o.y = fmaxf(0.f, (yv.y - mean) * scale + bet + xv.y);
    o.z = fmaxf(0.f, (yv.z - mean) * scale + bet + xv.z);
    o.w = fmaxf(0.f, (yv.w - mean) * scale + bet + xv.w);
    ((float4*)out)[i4] = o;
}

// ---------------- launch ------------------------------------------------------
extern "C" void kernel_launch(void* const* d_in, const int* in_sizes, int n_in,
                              void* d_out, int out_size) {
    const float* x     = (const float*)d_in[0];
    const float* A     = (const float*)d_in[1];
    const float* W     = (const float*)d_in[2];
    const float* wa    = (const float*)d_in[3];
    const float* ba    = (const float*)d_in[4];
    const float* wb    = (const float*)d_in[5];
    const float* bb    = (const float*)d_in[6];
    const float* wd    = (const float*)d_in[7];
    const float* bd    = (const float*)d_in[8];
    const float* gamma = (const float*)d_in[9];
    const float* beta  = (const float*)d_in[10];
    float* out = (float*)d_out;

    static bool attr_set = false;
    if (!attr_set) {
        cudaFuncSetAttribute(k_attn_mma, cudaFuncAttributeMaxDynamicSharedMemorySize,
                             KA_SMEM_FLOATS * sizeof(float));
        cudaFuncSetAttribute(k_fused_mma, cudaFuncAttributeMaxDynamicSharedMemorySize,
                             FM_SMEM_FLOATS * sizeof(float));
        attr_set = true;
    }

    k_prep<<<472, 256>>>(wd, bd);
    k_attn_mma<<<dim3(NS, 3), 256, KA_SMEM_FLOATS * sizeof(float)>>>(x, wa, ba, wb, bb);
    k_softmax<<<NS, 32>>>(A, W);
    k_fused_mma<<<dim3(Nn, 60), 256, FM_SMEM_FLOATS * sizeof(float)>>>(x, wd);
    k_final<<<30000, 256>>>(x, gamma, beta, out);
}

// round 17
// speedup vs baseline: 1.0419x; 1.0419x over previous
#include <cuda_runtime.h>
#include <cstdint>

// Problem constants
#define Nn 64
#define Cc 64
#define Tt 300
#define Vv 25
#define Ss 3
#define TV 7500
#define NS 192
#define CNT_BN 480000.0f
#define EPS_BN 1e-5f

// ---------------- scratch -----------------------------------------------------
__device__ float g_scores[NS * 625];
__device__ float g_adapt[NS * 700];               // [ns][v][w pad 28]
__device__ float g_y[(size_t)Nn * Cc * TV];
__device__ float g_bdsum[Cc];
__device__ float g_stats[2 * Cc];

#define MMA_TF32(d, a0, a1, a2, a3, b0, b1)                                   \
    asm volatile(                                                              \
        "mma.sync.aligned.m16n8k8.row.col.f32.tf32.tf32.f32 "                  \
        "{%0,%1,%2,%3}, {%4,%5,%6,%7}, {%8,%9}, {%0,%1,%2,%3};"                \
        : "+f"((d)[0]), "+f"((d)[1]), "+f"((d)[2]), "+f"((d)[3])               \
        : "r"(a0), "r"(a1), "r"(a2), "r"(a3), "r"(b0), "r"(b1))

// ---------------- K0: prep ----------------------------------------------------
__global__ void k_prep(const float* __restrict__ wd, const float* __restrict__ bd) {
    int idx = blockIdx.x * 256 + threadIdx.x;
    if (idx < NS * 625) g_scores[idx] = 0.f;
    if (idx < Cc) g_bdsum[idx] = bd[idx] + bd[64 + idx] + bd[128 + idx];
    if (idx < 2 * Cc) g_stats[idx] = 0.f;
}

// ---------------- K1: tensor projection + scores, shift-only (R14 best) -------
#define KA_SMEM_FLOATS 24992
__global__ void __launch_bounds__(256, 2)
k_attn_mma(const float* __restrict__ x,
           const float* __restrict__ wa, const float* __restrict__ ba,
           const float* __restrict__ wb, const float* __restrict__ bb) {
    extern __shared__ float sm[];
    float* wabT = sm;             // [32][68]
    float* bias = sm + 2176;      // [32]
    float* xs   = sm + 2208;      // 2 x [64][136] : [c][tp*32+v]
    float* abA  = sm + 19616;     // [32][84]
    float* abB  = sm + 22304;     // [32][84]

    int ns = blockIdx.x;
    int n = ns / Ss, s = ns - n * Ss;
    int tid = threadIdx.x;
    int wid = tid >> 5, lane = tid & 31;
    int g = lane >> 2, tig = lane & 3;

    for (int j = tid; j < 2048; j += 256) {
        int row = j >> 6, k = j & 63;
        wabT[row * 68 + k] = (row < 16) ? wa[(s * 16 + row) * 64 + k]
                                        : wb[(s * 16 + row - 16) * 64 + k];
    }
    if (tid < 32) bias[tid] = (tid < 16) ? ba[s * 16 + tid] : bb[s * 16 + tid - 16];

    const float* xn = x + (size_t)n * Cc * TV;
    int tcb = blockIdx.y * 100;

    if (lane < 25) {
#pragma unroll 1
        for (int rr = 0; rr < 8; rr++) {
            int c = wid * 8 + rr;
            const float* xg = xn + (size_t)c * TV + tcb * 25;
            float* xb = xs + c * 136;
#pragma unroll
            for (int tp = 0; tp < 4; tp++)
                xb[tp * 32 + lane] = xg[tp * 25 + lane];
        }
    }
    __syncthreads();

    float sc[4] = {0.f, 0.f, 0.f, 0.f};
    int smt = wid >> 2, snt = wid & 3;

    for (int b = 0; b < 25; b++) {
        int buf = b & 1;
        float* xb  = xs + buf * 8704;
        float* xnb = xs + (buf ^ 1) * 8704;

        if (b < 24 && lane < 25) {
            int tb = tcb + (b + 1) * 4;
#pragma unroll 1
            for (int rr = 0; rr < 8; rr++) {
                int c = wid * 8 + rr;
                const float* xg = xn + (size_t)c * TV + tb * 25;
                float* xo = xnb + c * 136;
#pragma unroll
                for (int tp = 0; tp < 4; tp++)
                    xo[tp * 32 + lane] = xg[tp * 25 + lane];
            }
        }
        float dd[2][2][4];
#pragma unroll
        for (int mt = 0; mt < 2; mt++)
#pragma unroll
            for (int lnt = 0; lnt < 2; lnt++)
#pragma unroll
                for (int e = 0; e < 4; e++) dd[mt][lnt][e] = 0.f;
#pragma unroll
        for (int ks = 0; ks < 8; ks++) {
            int k0 = ks * 8;
            uint32_t af[2][4];
#pragma unroll
            for (int mt = 0; mt < 2; mt++) {
                int r = mt * 16 + g;
                af[mt][0] = __float_as_uint(wabT[r * 68 + k0 + tig]);
                af[mt][1] = __float_as_uint(wabT[(r + 8) * 68 + k0 + tig]);
                af[mt][2] = __float_as_uint(wabT[r * 68 + k0 + 4 + tig]);
                af[mt][3] = __float_as_uint(wabT[(r + 8) * 68 + k0 + 4 + tig]);
            }
#pragma unroll
            for (int lnt = 0; lnt < 2; lnt++) {
                int col = (wid * 2 + lnt) * 8 + g;
                uint32_t b0 = __float_as_uint(xb[(k0 + tig) * 136 + col]);
                uint32_t b1 = __float_as_uint(xb[(k0 + 4 + tig) * 136 + col]);
#pragma unroll
                for (int mt = 0; mt < 2; mt++)
                    MMA_TF32(dd[mt][lnt], af[mt][0], af[mt][1], af[mt][2], af[mt][3], b0, b1);
            }
        }
#pragma unroll
        for (int mt = 0; mt < 2; mt++) {
            float* dst = mt ? abB : abA;
#pragma unroll
            for (int lnt = 0; lnt < 2; lnt++)
#pragma unroll
                for (int e = 0; e < 4; e++) {
                    int i2 = g + ((e >> 1) << 3);
                    int cg = (wid * 2 + lnt) * 8 + tig * 2 + (e & 1);
                    int v = cg & 31, tp = cg >> 5;
                    if (v < 25)
                        dst[v * 84 + i2 * 4 + tp] = dd[mt][lnt][e] + bias[mt * 16 + i2];
                }
        }
        __syncthreads();

        {
            int va = smt * 16 + g;
            int wcol = snt * 8 + g;
#pragma unroll
            for (int ks = 0; ks < 8; ks++) {
                int k0 = ks * 8;
                uint32_t a0 = __float_as_uint(abA[va * 84 + k0 + tig]);
                uint32_t a1 = __float_as_uint(abA[(va + 8) * 84 + k0 + tig]);
                uint32_t a2 = __float_as_uint(abA[va * 84 + k0 + 4 + tig]);
                uint32_t a3 = __float_as_uint(abA[(va + 8) * 84 + k0 + 4 + tig]);
                uint32_t b0 = __float_as_uint(abB[wcol * 84 + k0 + tig]);
                uint32_t b1 = __float_as_uint(abB[wcol * 84 + k0 + 4 + tig]);
                MMA_TF32(sc, a0, a1, a2, a3, b0, b1);
            }
        }
        __syncthreads();
    }

    {
        int v = smt * 16 + g;
        int w = snt * 8 + tig * 2;
        float* gs = g_scores + ns * 625;
        if (v < 25) {
            if (w < 25)     atomicAdd(&gs[v * 25 + w], sc[0]);
            if (w + 1 < 25) atomicAdd(&gs[v * 25 + w + 1], sc[1]);
        }
        if (v + 8 < 25) {
            if (w < 25)     atomicAdd(&gs[(v + 8) * 25 + w], sc[2]);
            if (w + 1 < 25) atomicAdd(&gs[(v + 8) * 25 + w + 1], sc[3]);
        }
    }
}

// ---------------- K2: softmax + adapt (padded 28) -----------------------------
__global__ void k_softmax(const float* __restrict__ A, const float* __restrict__ W) {
    int ns = blockIdx.x;
    int s = ns % Ss;
    int w = threadIdx.x;
    if (w >= 28) return;
    if (w >= Vv) {
#pragma unroll
        for (int v = 0; v < Vv; v++) g_adapt[ns * 700 + v * 28 + w] = 0.f;
        return;
    }
    float col[Vv];
    const float inv = 1.f / 4800.f;
    float m = -1e30f;
#pragma unroll
    for (int v = 0; v < Vv; v++) {
        col[v] = g_scores[ns * 625 + v * 25 + w] * inv;
        m = fmaxf(m, col[v]);
    }
    float sum = 0.f;
#pragma unroll
    for (int v = 0; v < Vv; v++) { col[v] = __expf(col[v] - m); sum += col[v]; }
    float r = 1.f / sum;
#pragma unroll
    for (int v = 0; v < Vv; v++) {
        int off = s * 625 + v * 25 + w;
        g_adapt[ns * 700 + v * 28 + w] = A[off] + W[off] + col[v] * r;
    }
}

// ---------------- K3: all-tensor fused (R13 best: specialized warps) ----------
// grid (64, 60). block 256. Layouts (floats):
//   xs  2 x 1440 @0      [cc]{180}[tp]{36}[(v&3)]{8}[v>>2]
//   zt  2 x 3264 @2880   [k][col pad 136]
//   wdf 2 x 1536 @9408   [ot*32+lane][12]
//   adT 3456 @12480      [s]{1152}[w]{36}[(v&3)]{8}[v>>2]
// Phase 1: warps 6-7 stage x(c+1); warps 0-5 z-MMA (s=wid>>1, 2/1 unit split).
// Phase 2: GEMM otile=wid&3 m16, nhalf=wid>>2 (8 nt), wdf prefetch.
#define FM_SMEM_FLOATS 15936
#define XS0 0
#define ZT0 2880
#define WDF0 9408
#define AD0 12480
__global__ void __launch_bounds__(256, 3)
k_fused_mma(const float* __restrict__ x, const float* __restrict__ wd) {
    extern __shared__ float dsm[];
    float* ysm = dsm;

    int n = blockIdx.x;
    int t0 = blockIdx.y * 5;
    int tid = threadIdx.x;
    int wid = tid >> 5, lane = tid & 31;
    int g = lane >> 2, tig = lane & 3;

    float d[8][4];
#pragma unroll
    for (int nt = 0; nt < 8; nt++)
#pragma unroll
        for (int e = 0; e < 4; e++) d[nt][e] = 0.f;

    int otile = wid & 3, nhalf = wid >> 2;
    int col0 = nhalf * 64;

    // ---- prologue: adT, xs (both bufs zero + chunk0 data), wdf(0) ----
    for (int j = tid; j < 3456; j += 256) {
        int s = j / 1152, r = j - s * 1152;
        int w = r / 36, i = r - w * 36;
        float val = 0.f;
        if (i < 32 && w < 25) {
            int v = (i & 7) * 4 + (i >> 3);
            if (v < 25) val = g_adapt[n * 2100 + s * 700 + v * 28 + w];
        }
        dsm[AD0 + j] = val;
    }
    for (int j = tid; j < 2880; j += 256) dsm[XS0 + j] = 0.f;
    __syncthreads();
    if (lane < 25) {
        int tigv = lane & 3, uv = lane >> 2;
        for (int cc = wid; cc < 8; cc += 8) {
            const float* xg = x + (size_t)(n * Cc + cc) * TV + t0 * 25;
            float* xb = dsm + XS0 + cc * 180;
#pragma unroll
            for (int tp = 0; tp < 5; tp++)
                xb[tp * 36 + tigv * 8 + uv] = xg[tp * 25 + lane];
        }
    }
    {   // wdf(0)
        float* wdn = dsm + WDF0;
        int ot = wid & 3, hf = wid >> 2;
#pragma unroll
        for (int q2 = 0; q2 < 6; q2++) {
            int i = hf * 6 + q2;
            int reg = i & 3, ks2 = i >> 2;
            int o = ot * 16 + g + ((reg & 1) << 3);
            int kk = ks2 * 8 + tig + ((reg >> 1) << 2);
            wdn[(ot * 32 + lane) * 12 + i] =
                wd[(size_t)(((kk >> 3) << 6) + o) * 64 + (kk & 7)];
        }
    }
    __syncthreads();

    for (int c = 0; c < 8; c++) {
        int buf = c & 1, nbuf = buf ^ 1;
        // ---- phase 1: warps 6-7 stage x(c+1); warps 0-5 z-MMA(c) ----
        if (wid >= 6) {
            if (c < 7 && lane < 25) {
                int c0n = (c + 1) * 8;
                int tigv = lane & 3, uv = lane >> 2;
                float* xsn = dsm + XS0 + nbuf * 1440;
                int ccb = (wid - 6) * 4;
#pragma unroll
                for (int c2 = 0; c2 < 4; c2++) {
                    const float* xg = x + (size_t)(n * Cc + c0n + ccb + c2) * TV + t0 * 25;
                    float* xb = xsn + (ccb + c2) * 180;
#pragma unroll
                    for (int tp = 0; tp < 5; tp++)
                        xb[tp * 36 + tigv * 8 + uv] = xg[tp * 25 + lane];
                }
            }
        } else {
            const float* xsb = dsm + XS0 + buf * 1440;
            float* ztb = dsm + ZT0 + buf * 3264;
            int s = wid >> 1, mg = wid & 1;
            const float* adTs = dsm + AD0 + s * 1152;
            int nmt = mg ? 1 : 2;
#pragma unroll 2
            for (int mi = 0; mi < nmt; mi++) {
                int mt = mg ? 2 : mi;
                int m0 = mt * 16 + g, m1 = m0 + 8;
                int cc0 = m0 / 5, tp0 = m0 - cc0 * 5;
                bool hv = (m1 < 40);
                int m1c = hv ? m1 : 0;
                int cc1 = m1c / 5, tp1 = m1c - cc1 * 5;
                float lo[8], hi[8];
                const float* pa = xsb + cc0 * 180 + tp0 * 36 + tig * 8;
                *(float4*)&lo[0] = *(const float4*)pa;
                *(float4*)&lo[4] = *(const float4*)(pa + 4);
                if (hv) {
                    const float* pb = xsb + cc1 * 180 + tp1 * 36 + tig * 8;
                    *(float4*)&hi[0] = *(const float4*)pb;
                    *(float4*)&hi[4] = *(const float4*)(pb + 4);
                } else {
#pragma unroll
                    for (int u = 0; u < 8; u++) hi[u] = 0.f;
                }
#pragma unroll
                for (int nt = 0; nt < 4; nt++) {
                    float adv[8];
                    const float* pc = adTs + (nt * 8 + g) * 36 + tig * 8;
                    *(float4*)&adv[0] = *(const float4*)pc;
                    *(float4*)&adv[4] = *(const float4*)(pc + 4);
                    float dz[4] = {0.f, 0.f, 0.f, 0.f};
#pragma unroll
                    for (int ks = 0; ks < 4; ks++) {
                        MMA_TF32(dz,
                                 __float_as_uint(lo[2 * ks]), __float_as_uint(hi[2 * ks]),
                                 __float_as_uint(lo[2 * ks + 1]), __float_as_uint(hi[2 * ks + 1]),
                                 __float_as_uint(adv[2 * ks]), __float_as_uint(adv[2 * ks + 1]));
                    }
                    int w0c = nt * 8 + tig * 2;
                    if (w0c < 25)     ztb[(s * 8 + cc0) * 136 + tp0 * 25 + w0c] = dz[0];
                    if (w0c + 1 < 25) ztb[(s * 8 + cc0) * 136 + tp0 * 25 + w0c + 1] = dz[1];
                    if (hv) {
                        if (w0c < 25)     ztb[(s * 8 + cc1) * 136 + tp1 * 25 + w0c] = dz[2];
                        if (w0c + 1 < 25) ztb[(s * 8 + cc1) * 136 + tp1 * 25 + w0c + 1] = dz[3];
                    }
                }
            }
        }
        __syncthreads();   // the ONLY barrier per chunk

        // ---- phase 2: wdf stage (c+1) + gemm(c) ----
        if (c < 7) {
            int c0n = (c + 1) * 8;
            float* wdn = dsm + WDF0 + nbuf * 1536;
            int ot = wid & 3, hf = wid >> 2;
#pragma unroll
            for (int q2 = 0; q2 < 6; q2++) {
                int i = hf * 6 + q2;
                int reg = i & 3, ks2 = i >> 2;
                int o = ot * 16 + g + ((reg & 1) << 3);
                int kk = ks2 * 8 + tig + ((reg >> 1) << 2);
                wdn[(ot * 32 + lane) * 12 + i] =
                    wd[(size_t)(((kk >> 3) << 6) + o) * 64 + c0n + (kk & 7)];
            }
        }
        {
            const float* ztb = dsm + ZT0 + buf * 3264;
            const float* wdb = dsm + WDF0 + buf * 1536;
            float afr[12];
            const float* pw = wdb + (otile * 32 + lane) * 12;
            *(float4*)&afr[0] = *(const float4*)pw;
            *(float4*)&afr[4] = *(const float4*)(pw + 4);
            *(float4*)&afr[8] = *(const float4*)(pw + 8);
#pragma unroll
            for (int ks = 0; ks < 3; ks++) {
                int k0 = ks * 8;
                uint32_t a0 = __float_as_uint(afr[ks * 4 + 0]);
                uint32_t a1 = __float_as_uint(afr[ks * 4 + 1]);
                uint32_t a2 = __float_as_uint(afr[ks * 4 + 2]);
                uint32_t a3 = __float_as_uint(afr[ks * 4 + 3]);
#pragma unroll
                for (int nt = 0; nt < 8; nt++) {
                    int nc = col0 + nt * 8 + g;
                    uint32_t b0 = __float_as_uint(ztb[(k0 + tig) * 136 + nc]);
                    uint32_t b1 = __float_as_uint(ztb[(k0 + 4 + tig) * 136 + nc]);
                    MMA_TF32(d[nt], a0, a1, a2, a3, b0, b1);
                }
            }
        }
    }

    // ---- epilogue ----
    __syncthreads();
#pragma unroll
    for (int nt = 0; nt < 8; nt++) {
        int colb = col0 + nt * 8 + tig * 2;
        int r0 = otile * 16 + g;
        ysm[r0 * 132 + colb]           = d[nt][0];
        ysm[r0 * 132 + colb + 1]       = d[nt][1];
        ysm[(r0 + 8) * 132 + colb]     = d[nt][2];
        ysm[(r0 + 8) * 132 + colb + 1] = d[nt][3];
    }
    __syncthreads();
#pragma unroll 1
    for (int rr = 0; rr < 8; rr++) {
        int o = wid * 8 + rr;
        float bias = g_bdsum[o];
        float s1 = 0.f, s2 = 0.f;
        float* yp = g_y + (size_t)(n * Cc + o) * TV + t0 * 25;
        for (int col = lane; col < 125; col += 32) {
            float v = ysm[o * 132 + col] + bias;
            yp[col] = v;
            s1 += v; s2 += v * v;
        }
#pragma unroll
        for (int dd2 = 16; dd2 > 0; dd2 >>= 1) {
            s1 += __shfl_xor_sync(0xffffffffu, s1, dd2);
            s2 += __shfl_xor_sync(0xffffffffu, s2, dd2);
        }
        if (lane == 0) {
            atomicAdd(&g_stats[o], s1);
            atomicAdd(&g_stats[64 + o], s2);
        }
    }
}

// ---------------- K4: normalize + gamma/beta + residual + relu ----------------
__global__ void k_final(const float* __restrict__ x,
                        const float* __restrict__ gamma, const float* __restrict__ beta,
                        float* __restrict__ out) {
    int i4 = blockIdx.x * 256 + threadIdx.x;
    int c = (i4 / 1875) & 63;
    float s1 = g_stats[c], s2 = g_stats[64 + c];
    float mean = s1 / CNT_BN;
    float var = s2 / CNT_BN - mean * mean;
    float scale = gamma[c] * rsqrtf(var + EPS_BN);
    float bet = beta[c];
    float4 yv = ((const float4*)g_y)[i4];
    float4 xv = ((const float4*)x)[i4];
    float4 o;
    o.x = fmaxf(0.f, (yv.x - mean) * scale + bet + xv.x);
    o.y = fmaxf(0.f, (yv.y - mean) * scale + bet + xv.y);
    o.z = fmaxf(0.f, (yv.z - mean) * scale + bet + xv.z);
    o.w = fmaxf(0.f, (yv.w - mean) * scale + bet + xv.w);
    ((float4*)out)[i4] = o;
}

// ---------------- launch ------------------------------------------------------
extern "C" void kernel_launch(void* const* d_in, const int* in_sizes, int n_in,
                              void* d_out, int out_size) {
    const float* x     = (const float*)d_in[0];
    const float* A     = (const float*)d_in[1];
    const float* W     = (const float*)d_in[2];
    const float* wa    = (const float*)d_in[3];
    const float* ba    = (const float*)d_in[4];
    const float* wb    = (const float*)d_in[5];
    const float* bb    = (const float*)d_in[6];
    const float* wd    = (const float*)d_in[7];
    const float* bd    = (const float*)d_in[8];
    const float* gamma = (const float*)d_in[9];
    const float* beta  = (const float*)d_in[10];
    float* out = (float*)d_out;

    static bool attr_set = false;
    if (!attr_set) {
        cudaFuncSetAttribute(k_attn_mma, cudaFuncAttributeMaxDynamicSharedMemorySize,
                             KA_SMEM_FLOATS * sizeof(float));
        cudaFuncSetAttribute(k_fused_mma, cudaFuncAttributeMaxDynamicSharedMemorySize,
                             FM_SMEM_FLOATS * sizeof(float));
        attr_set = true;
    }

    k_prep<<<472, 256>>>(wd, bd);
    k_attn_mma<<<dim3(NS, 3), 256, KA_SMEM_FLOATS * sizeof(float)>>>(x, wa, ba, wb, bb);
    k_softmax<<<NS, 32>>>(A, W);
    k_fused_mma<<<dim3(Nn, 60), 256, FM_SMEM_FLOATS * sizeof(float)>>>(x, wd);
    k_final<<<30000, 256>>>(x, gamma, beta, out);
}